// round 2
// baseline (speedup 1.0000x reference)
#include <cuda_runtime.h>
#include <cuda_bf16.h>
#include <cstdint>

// Problem constants
#define BB 2
#define TT 2048
#define DD 1024
#define HH 16
#define DH 64
#define MM (BB*TT)          // 4096
#define N_QKV (3*DD)        // 3072

// Scratch (device globals — no runtime allocation allowed)
__device__ float gQ[BB*HH*TT*DH];   // [B,H,T,dh]
__device__ float gK[BB*HH*TT*DH];
__device__ float gV[BB*HH*TT*DH];
__device__ float gA[BB*TT*DD];      // merged-head attention output [B,T,D]

// ---------------------------------------------------------------------------
// GEMM 1: qkv = x @ W_attn + b_attn, scatter into gQ/gK/gV ([B,H,T,dh])
// C[M=4096, N=3072], K=1024. 128x128 tile, BK=8, 256 threads, 8x8 per thread.
// ---------------------------------------------------------------------------
__global__ __launch_bounds__(256) void gemm_qkv_kernel(
    const float* __restrict__ X, const float* __restrict__ W,
    const float* __restrict__ bias)
{
    const int K = DD, N = N_QKV;
    const int n0 = blockIdx.x * 128;
    const int m0 = blockIdx.y * 128;
    const int tid = threadIdx.x;
    const int tx = tid & 15, ty = tid >> 4;

    __shared__ float As[8][128];
    __shared__ float Bs[8][128];

    float acc[8][8];
#pragma unroll
    for (int i = 0; i < 8; i++)
#pragma unroll
        for (int j = 0; j < 8; j++) acc[i][j] = 0.f;

    const int arow  = tid >> 1;          // 0..127
    const int acol4 = (tid & 1) * 4;     // 0 or 4
    const int brow  = tid >> 5;          // 0..7
    const int bcol  = (tid & 31) * 4;    // 0..124

    const float* Aptr = X + (size_t)(m0 + arow) * K + acol4;
    const float* Bptr = W + (size_t)brow * N + n0 + bcol;

    for (int k0 = 0; k0 < K; k0 += 8) {
        float4 av = *(const float4*)(Aptr + k0);
        float4 bv = *(const float4*)(Bptr + (size_t)k0 * N);
        __syncthreads();
        As[acol4 + 0][arow] = av.x;
        As[acol4 + 1][arow] = av.y;
        As[acol4 + 2][arow] = av.z;
        As[acol4 + 3][arow] = av.w;
        *(float4*)&Bs[brow][bcol] = bv;
        __syncthreads();
#pragma unroll
        for (int kk = 0; kk < 8; kk++) {
            float rm[8], rn[8];
            *(float4*)&rm[0] = *(const float4*)&As[kk][ty * 8];
            *(float4*)&rm[4] = *(const float4*)&As[kk][ty * 8 + 4];
            *(float4*)&rn[0] = *(const float4*)&Bs[kk][tx * 8];
            *(float4*)&rn[4] = *(const float4*)&Bs[kk][tx * 8 + 4];
#pragma unroll
            for (int i = 0; i < 8; i++)
#pragma unroll
                for (int j = 0; j < 8; j++) acc[i][j] += rm[i] * rn[j];
        }
    }

    // Epilogue: scatter to Q/K/V in [B,H,T,dh]. Whole 128-col block lands in
    // one of q/k/v (n0 multiple of 128, 1024 % 128 == 0).
    const int which = n0 >> 10;
    float* dst = (which == 0) ? gQ : ((which == 1) ? gK : gV);
#pragma unroll
    for (int i = 0; i < 8; i++) {
        const int m = m0 + ty * 8 + i;
        const int b = m >> 11, t = m & (TT - 1);
#pragma unroll
        for (int j = 0; j < 8; j++) {
            const int n = n0 + tx * 8 + j;
            const float v = acc[i][j] + bias[n];
            const int dcol = n & (DD - 1);
            const int h = dcol >> 6, dd = dcol & (DH - 1);
            dst[(((size_t)(b * HH + h) * TT) + t) * DH + dd] = v;
        }
    }
}

// ---------------------------------------------------------------------------
// GEMM 2: out = gA @ W_proj + b_proj. C[4096, 1024], K=1024.
// ---------------------------------------------------------------------------
__global__ __launch_bounds__(256) void gemm_proj_kernel(
    const float* __restrict__ W, const float* __restrict__ bias,
    float* __restrict__ C)
{
    const int K = DD, N = DD;
    const float* X = gA;
    const int n0 = blockIdx.x * 128;
    const int m0 = blockIdx.y * 128;
    const int tid = threadIdx.x;
    const int tx = tid & 15, ty = tid >> 4;

    __shared__ float As[8][128];
    __shared__ float Bs[8][128];

    float acc[8][8];
#pragma unroll
    for (int i = 0; i < 8; i++)
#pragma unroll
        for (int j = 0; j < 8; j++) acc[i][j] = 0.f;

    const int arow  = tid >> 1;
    const int acol4 = (tid & 1) * 4;
    const int brow  = tid >> 5;
    const int bcol  = (tid & 31) * 4;

    const float* Aptr = X + (size_t)(m0 + arow) * K + acol4;
    const float* Bptr = W + (size_t)brow * N + n0 + bcol;

    for (int k0 = 0; k0 < K; k0 += 8) {
        float4 av = *(const float4*)(Aptr + k0);
        float4 bv = *(const float4*)(Bptr + (size_t)k0 * N);
        __syncthreads();
        As[acol4 + 0][arow] = av.x;
        As[acol4 + 1][arow] = av.y;
        As[acol4 + 2][arow] = av.z;
        As[acol4 + 3][arow] = av.w;
        *(float4*)&Bs[brow][bcol] = bv;
        __syncthreads();
#pragma unroll
        for (int kk = 0; kk < 8; kk++) {
            float rm[8], rn[8];
            *(float4*)&rm[0] = *(const float4*)&As[kk][ty * 8];
            *(float4*)&rm[4] = *(const float4*)&As[kk][ty * 8 + 4];
            *(float4*)&rn[0] = *(const float4*)&Bs[kk][tx * 8];
            *(float4*)&rn[4] = *(const float4*)&Bs[kk][tx * 8 + 4];
#pragma unroll
            for (int i = 0; i < 8; i++)
#pragma unroll
                for (int j = 0; j < 8; j++) acc[i][j] += rm[i] * rn[j];
        }
    }

#pragma unroll
    for (int i = 0; i < 8; i++) {
        const int m = m0 + ty * 8 + i;
        float* crow = C + (size_t)m * N + n0 + tx * 8;
        float4 o0, o1;
        o0.x = acc[i][0] + bias[n0 + tx * 8 + 0];
        o0.y = acc[i][1] + bias[n0 + tx * 8 + 1];
        o0.z = acc[i][2] + bias[n0 + tx * 8 + 2];
        o0.w = acc[i][3] + bias[n0 + tx * 8 + 3];
        o1.x = acc[i][4] + bias[n0 + tx * 8 + 4];
        o1.y = acc[i][5] + bias[n0 + tx * 8 + 5];
        o1.z = acc[i][6] + bias[n0 + tx * 8 + 6];
        o1.w = acc[i][7] + bias[n0 + tx * 8 + 7];
        *(float4*)(crow)     = o0;
        *(float4*)(crow + 4) = o1;
    }
}

// ---------------------------------------------------------------------------
// Flash attention (causal), fp32. grid = (B*H, T/128), 128 threads.
// One thread = one query row. q row + acc in registers; K/V tiles (64 keys)
// broadcast from smem as float4. Online softmax in chunks of 16 keys.
// ---------------------------------------------------------------------------
__global__ __launch_bounds__(128) void flash_kernel()
{
    const int bh = blockIdx.x;       // 0..31
    const int qtile = blockIdx.y;    // 0..15
    const int tid = threadIdx.x;
    const int qr = qtile * 128 + tid;          // row within head

    const float4* qptr = (const float4*)(gQ + ((size_t)bh * TT + qr) * DH);
    float4 q[16];
#pragma unroll
    for (int i = 0; i < 16; i++) q[i] = __ldg(qptr + i);

    float acc[64];
#pragma unroll
    for (int d = 0; d < 64; d++) acc[d] = 0.f;
    float m_run = -1e30f, l_run = 0.f;

    __shared__ float4 Ks[64 * 16];
    __shared__ float4 Vs[64 * 16];

    const int ntiles = 2 * qtile + 2;   // covers keys up to max qr in block
    for (int tk = 0; tk < ntiles; tk++) {
        const int j0 = tk * 64;
        const float4* kp = (const float4*)(gK + ((size_t)bh * TT + j0) * DH);
        const float4* vp = (const float4*)(gV + ((size_t)bh * TT + j0) * DH);
        __syncthreads();
#pragma unroll
        for (int i = 0; i < 8; i++) {
            Ks[tid + i * 128] = __ldg(kp + tid + i * 128);
            Vs[tid + i * 128] = __ldg(vp + tid + i * 128);
        }
        __syncthreads();

        for (int c = 0; c < 4; c++) {
            const int jb = c * 16;
            if (j0 + jb > qr) break;    // fully masked for this thread

            float s[16];
            float mx = -1e30f;
#pragma unroll
            for (int jj = 0; jj < 16; jj++) {
                const float4* kr = &Ks[(jb + jj) * 16];
                float sv = 0.f;
#pragma unroll
                for (int d4 = 0; d4 < 16; d4++) {
                    float4 kk = kr[d4];
                    sv += q[d4].x * kk.x + q[d4].y * kk.y
                        + q[d4].z * kk.z + q[d4].w * kk.w;
                }
                sv *= 0.125f;           // 1/sqrt(64)
                if (j0 + jb + jj > qr) sv = -1e30f;
                s[jj] = sv;
                mx = fmaxf(mx, sv);
            }
            const float m_new = fmaxf(m_run, mx);
            const float corr = __expf(m_run - m_new);
            float psum = 0.f;
#pragma unroll
            for (int jj = 0; jj < 16; jj++) {
                s[jj] = __expf(s[jj] - m_new);
                psum += s[jj];
            }
            l_run = l_run * corr + psum;
#pragma unroll
            for (int d = 0; d < 64; d++) acc[d] *= corr;
#pragma unroll
            for (int jj = 0; jj < 16; jj++) {
                const float4* vr = &Vs[(jb + jj) * 16];
                const float p = s[jj];
#pragma unroll
                for (int d4 = 0; d4 < 16; d4++) {
                    float4 vv = vr[d4];
                    acc[d4 * 4 + 0] += p * vv.x;
                    acc[d4 * 4 + 1] += p * vv.y;
                    acc[d4 * 4 + 2] += p * vv.z;
                    acc[d4 * 4 + 3] += p * vv.w;
                }
            }
            m_run = m_new;
        }
    }

    // Write merged-head output: gA[b, t=qr, h*64 + d]
    const float inv = 1.f / l_run;
    const int b = bh >> 4, h = bh & 15;
    float4* op = (float4*)(gA + ((size_t)(b * TT + qr)) * DD + h * DH);
#pragma unroll
    for (int d4 = 0; d4 < 16; d4++) {
        float4 o;
        o.x = acc[d4 * 4 + 0] * inv;
        o.y = acc[d4 * 4 + 1] * inv;
        o.z = acc[d4 * 4 + 2] * inv;
        o.w = acc[d4 * 4 + 3] * inv;
        op[d4] = o;
    }
}

// ---------------------------------------------------------------------------
// Launcher
// ---------------------------------------------------------------------------
extern "C" void kernel_launch(void* const* d_in, const int* in_sizes, int n_in,
                              void* d_out, int out_size)
{
    const float* x      = (const float*)d_in[0];
    const float* W_attn = (const float*)d_in[1];
    const float* b_attn = (const float*)d_in[2];
    const float* W_proj = (const float*)d_in[3];
    const float* b_proj = (const float*)d_in[4];
    float* out = (float*)d_out;

    dim3 g1(N_QKV / 128, MM / 128);     // 24 x 32
    gemm_qkv_kernel<<<g1, 256>>>(x, W_attn, b_attn);

    dim3 g2(BB * HH, TT / 128);         // 32 x 16
    flash_kernel<<<g2, 128>>>();

    dim3 g3(DD / 128, MM / 128);        // 8 x 32
    gemm_proj_kernel<<<g3, 256>>>(W_proj, b_proj, out);
}